// round 1
// baseline (speedup 1.0000x reference)
#include <cuda_runtime.h>

// Problem constants
#define DD 300
#define LL 128
#define BC 2048            // B*C = 32*64
#define WARPS_PER_BLOCK 8
#define THREADS (WARPS_PER_BLOCK * 32)

__global__ void __launch_bounds__(THREADS)
hcmp_kernel(const float* __restrict__ x,
            const float* __restrict__ y,
            float* __restrict__ out)
{
    const int warp = (blockIdx.x * WARPS_PER_BLOCK) + (threadIdx.x >> 5);
    const int lane = threadIdx.x & 31;
    if (warp >= BC) return;

    // Base of this (b,c) slab: D*L floats. Lane handles float4 covering
    // l in [4*lane, 4*lane+3]. Row stride per d = L floats = 32 float4.
    const float4* __restrict__ xp =
        reinterpret_cast<const float4*>(x + (size_t)warp * (DD * LL)) + lane;
    const float4* __restrict__ yp =
        reinterpret_cast<const float4*>(y + (size_t)warp * (DD * LL)) + lane;

    float sxx[4] = {0.f, 0.f, 0.f, 0.f};
    float syy[4] = {0.f, 0.f, 0.f, 0.f};
    float sxy[4] = {0.f, 0.f, 0.f, 0.f};
    float sl1[4] = {0.f, 0.f, 0.f, 0.f};
    float sdd[4] = {0.f, 0.f, 0.f, 0.f};

    #pragma unroll 4
    for (int d = 0; d < DD; d++) {
        float4 a = xp[d * (LL / 4)];
        float4 b = yp[d * (LL / 4)];

        float ax[4] = {a.x, a.y, a.z, a.w};
        float by[4] = {b.x, b.y, b.z, b.w};
        #pragma unroll
        for (int j = 0; j < 4; j++) {
            float xv = ax[j];
            float yv = by[j];
            float df = xv - yv;
            sxx[j] = fmaf(xv, xv, sxx[j]);
            syy[j] = fmaf(yv, yv, syy[j]);
            sxy[j] = fmaf(xv, yv, sxy[j]);
            sdd[j] = fmaf(df, df, sdd[j]);
            sl1[j] += fabsf(df);
        }
    }

    // Output row index: (b*C + c)*L + l == warp*L + l; 3 floats per row.
    #pragma unroll
    for (int j = 0; j < 4; j++) {
        int l = lane * 4 + j;
        float nx = fmaxf(sqrtf(sxx[j]), 1e-12f);
        float ny = fmaxf(sqrtf(syy[j]), 1e-12f);
        float cosv = sxy[j] / (nx * ny);

        float sq = sdd[j];
        if (sq < 1e-8f) sq += 1e-8f;   // revise_zero_data: add boundary, not clamp
        float l2 = sqrtf(sq);

        size_t o = ((size_t)warp * LL + l) * 3;
        out[o + 0] = cosv;
        out[o + 1] = l2;
        out[o + 2] = sl1[j];
    }
}

extern "C" void kernel_launch(void* const* d_in, const int* in_sizes, int n_in,
                              void* d_out, int out_size)
{
    const float* x = (const float*)d_in[0];
    const float* y = (const float*)d_in[1];
    float* out = (float*)d_out;

    dim3 grid(BC / WARPS_PER_BLOCK);   // 256 blocks
    dim3 block(THREADS);               // 256 threads = 8 warps
    hcmp_kernel<<<grid, block>>>(x, y, out);
}

// round 2
// speedup vs baseline: 1.0835x; 1.0835x over previous
#include <cuda_runtime.h>

// Problem constants
#define DD 300
#define LL 128
#define BC 2048                 // B*C = 32*64
#define NROWS (BC * LL)         // 262144 output rows
#define THREADS 256

__global__ void __launch_bounds__(THREADS)
hcmp_kernel(const float* __restrict__ x,
            const float* __restrict__ y,
            float* __restrict__ out)
{
    const int row = blockIdx.x * THREADS + threadIdx.x;   // (b*C+c)*L + l
    // slab = row >> 7 (the (b,c) pair), l = row & 127.
    // Element (slab, d, l) lives at slab*D*L + d*L + l.
    const size_t base = (size_t)(row >> 7) * (DD * LL) + (row & (LL - 1));
    const float* __restrict__ xp = x + base;
    const float* __restrict__ yp = y + base;

    float sxx = 0.f, syy = 0.f, sxy = 0.f, sl1 = 0.f, sdd = 0.f;

    #pragma unroll 10
    for (int d = 0; d < DD; d++) {
        float xv = __ldcs(xp + d * LL);
        float yv = __ldcs(yp + d * LL);
        float df = xv - yv;
        sxx = fmaf(xv, xv, sxx);
        syy = fmaf(yv, yv, syy);
        sxy = fmaf(xv, yv, sxy);
        sdd = fmaf(df, df, sdd);
        sl1 += fabsf(df);
    }

    float nx = fmaxf(sqrtf(sxx), 1e-12f);
    float ny = fmaxf(sqrtf(syy), 1e-12f);
    float cosv = sxy / (nx * ny);

    float sq = sdd;
    if (sq < 1e-8f) sq += 1e-8f;     // revise_zero_data
    float l2 = sqrtf(sq);

    const size_t o = (size_t)row * 3;
    out[o + 0] = cosv;
    out[o + 1] = l2;
    out[o + 2] = sl1;
}

extern "C" void kernel_launch(void* const* d_in, const int* in_sizes, int n_in,
                              void* d_out, int out_size)
{
    const float* x = (const float*)d_in[0];
    const float* y = (const float*)d_in[1];
    float* out = (float*)d_out;

    dim3 grid(NROWS / THREADS);    // 1024 blocks
    dim3 block(THREADS);
    hcmp_kernel<<<grid, block>>>(x, y, out);
}

// round 3
// speedup vs baseline: 1.1783x; 1.0875x over previous
#include <cuda_runtime.h>

// Problem constants
#define DD 300
#define LL 128
#define BC 2048                   // B*C = 32*64
#define NROWS (BC * LL)           // 262144 output rows
#define THREADS 256
#define NTHREADS_TOTAL (NROWS / 2)   // one thread per 2 rows
#define UB 6                      // d-batch: 300 = 6 * 50

__global__ void __launch_bounds__(THREADS, 4)
hcmp_kernel(const float* __restrict__ x,
            const float* __restrict__ y,
            float* __restrict__ out)
{
    const int t = blockIdx.x * THREADS + threadIdx.x;
    const int row0 = t * 2;                       // rows row0, row0+1
    const int slab = row0 >> 7;                   // (b*C + c)
    const int l0 = row0 & (LL - 1);               // even l

    // float2 view: element (slab, d, l0..l0+1) at x + slab*D*L + d*L + l0
    const float2* __restrict__ xp =
        reinterpret_cast<const float2*>(x + (size_t)slab * (DD * LL) + l0);
    const float2* __restrict__ yp =
        reinterpret_cast<const float2*>(y + (size_t)slab * (DD * LL) + l0);
    // stride per d in float2 units = L/2 = 64

    float sxx0 = 0.f, syy0 = 0.f, sxy0 = 0.f, sl10 = 0.f, sdd0 = 0.f;
    float sxx1 = 0.f, syy1 = 0.f, sxy1 = 0.f, sl11 = 0.f, sdd1 = 0.f;

    for (int d = 0; d < DD; d += UB) {
        float2 xa[UB], ya[UB];
        #pragma unroll
        for (int u = 0; u < UB; u++)
            xa[u] = __ldcs(xp + (d + u) * (LL / 2));
        #pragma unroll
        for (int u = 0; u < UB; u++)
            ya[u] = __ldcs(yp + (d + u) * (LL / 2));

        #pragma unroll
        for (int u = 0; u < UB; u++) {
            float xv0 = xa[u].x, yv0 = ya[u].x;
            float df0 = xv0 - yv0;
            sxx0 = fmaf(xv0, xv0, sxx0);
            syy0 = fmaf(yv0, yv0, syy0);
            sxy0 = fmaf(xv0, yv0, sxy0);
            sdd0 = fmaf(df0, df0, sdd0);
            sl10 += fabsf(df0);

            float xv1 = xa[u].y, yv1 = ya[u].y;
            float df1 = xv1 - yv1;
            sxx1 = fmaf(xv1, xv1, sxx1);
            syy1 = fmaf(yv1, yv1, syy1);
            sxy1 = fmaf(xv1, yv1, sxy1);
            sdd1 = fmaf(df1, df1, sdd1);
            sl11 += fabsf(df1);
        }
    }

    // Epilogue for both rows; outputs are 6 contiguous floats at row0*3.
    float nx0 = fmaxf(sqrtf(sxx0), 1e-12f);
    float ny0 = fmaxf(sqrtf(syy0), 1e-12f);
    float cos0 = sxy0 / (nx0 * ny0);
    float sq0 = sdd0;
    if (sq0 < 1e-8f) sq0 += 1e-8f;
    float l20 = sqrtf(sq0);

    float nx1 = fmaxf(sqrtf(sxx1), 1e-12f);
    float ny1 = fmaxf(sqrtf(syy1), 1e-12f);
    float cos1 = sxy1 / (nx1 * ny1);
    float sq1 = sdd1;
    if (sq1 < 1e-8f) sq1 += 1e-8f;
    float l21 = sqrtf(sq1);

    float* o = out + (size_t)row0 * 3;
    o[0] = cos0;
    o[1] = l20;
    o[2] = sl10;
    o[3] = cos1;
    o[4] = l21;
    o[5] = sl11;
}

extern "C" void kernel_launch(void* const* d_in, const int* in_sizes, int n_in,
                              void* d_out, int out_size)
{
    const float* x = (const float*)d_in[0];
    const float* y = (const float*)d_in[1];
    float* out = (float*)d_out;

    dim3 grid(NTHREADS_TOTAL / THREADS);   // 512 blocks
    dim3 block(THREADS);
    hcmp_kernel<<<grid, block>>>(x, y, out);
}

// round 4
// speedup vs baseline: 1.2042x; 1.0220x over previous
#include <cuda_runtime.h>

// Problem constants
#define DD 300
#define LL 128
#define BC 2048                   // B*C = 32*64
#define NROWS (BC * LL)           // 262144 output rows
#define THREADS 64                // small blocks => fine-grain scheduling
#define NTHREADS_TOTAL (NROWS / 2)   // one thread per 2 rows => 131072 threads
#define UB 6                      // d-batch: 300 = 6 * 50

__global__ void __launch_bounds__(THREADS, 16)
hcmp_kernel(const float* __restrict__ x,
            const float* __restrict__ y,
            float* __restrict__ out)
{
    const int t = blockIdx.x * THREADS + threadIdx.x;
    const int row0 = t * 2;                       // rows row0, row0+1
    const int slab = row0 >> 7;                   // (b*C + c)
    const int l0 = row0 & (LL - 1);               // even l

    // float2 view: element (slab, d, l0..l0+1) at x + slab*D*L + d*L + l0
    const float2* __restrict__ xp =
        reinterpret_cast<const float2*>(x + (size_t)slab * (DD * LL) + l0);
    const float2* __restrict__ yp =
        reinterpret_cast<const float2*>(y + (size_t)slab * (DD * LL) + l0);
    // stride per d in float2 units = L/2 = 64

    float sxx0 = 0.f, syy0 = 0.f, sxy0 = 0.f, sl10 = 0.f, sdd0 = 0.f;
    float sxx1 = 0.f, syy1 = 0.f, sxy1 = 0.f, sl11 = 0.f, sdd1 = 0.f;

    for (int d = 0; d < DD; d += UB) {
        float2 xa[UB], ya[UB];
        #pragma unroll
        for (int u = 0; u < UB; u++)
            xa[u] = __ldcs(xp + (d + u) * (LL / 2));
        #pragma unroll
        for (int u = 0; u < UB; u++)
            ya[u] = __ldcs(yp + (d + u) * (LL / 2));

        #pragma unroll
        for (int u = 0; u < UB; u++) {
            float xv0 = xa[u].x, yv0 = ya[u].x;
            float df0 = xv0 - yv0;
            sxx0 = fmaf(xv0, xv0, sxx0);
            syy0 = fmaf(yv0, yv0, syy0);
            sxy0 = fmaf(xv0, yv0, sxy0);
            sdd0 = fmaf(df0, df0, sdd0);
            sl10 += fabsf(df0);

            float xv1 = xa[u].y, yv1 = ya[u].y;
            float df1 = xv1 - yv1;
            sxx1 = fmaf(xv1, xv1, sxx1);
            syy1 = fmaf(yv1, yv1, syy1);
            sxy1 = fmaf(xv1, yv1, sxy1);
            sdd1 = fmaf(df1, df1, sdd1);
            sl11 += fabsf(df1);
        }
    }

    // Epilogue for both rows; outputs are 6 contiguous floats at row0*3.
    float nx0 = fmaxf(sqrtf(sxx0), 1e-12f);
    float ny0 = fmaxf(sqrtf(syy0), 1e-12f);
    float cos0 = sxy0 / (nx0 * ny0);
    float sq0 = sdd0;
    if (sq0 < 1e-8f) sq0 += 1e-8f;
    float l20 = sqrtf(sq0);

    float nx1 = fmaxf(sqrtf(sxx1), 1e-12f);
    float ny1 = fmaxf(sqrtf(syy1), 1e-12f);
    float cos1 = sxy1 / (nx1 * ny1);
    float sq1 = sdd1;
    if (sq1 < 1e-8f) sq1 += 1e-8f;
    float l21 = sqrtf(sq1);

    float* o = out + (size_t)row0 * 3;
    o[0] = cos0;
    o[1] = l20;
    o[2] = sl10;
    o[3] = cos1;
    o[4] = l21;
    o[5] = sl11;
}

extern "C" void kernel_launch(void* const* d_in, const int* in_sizes, int n_in,
                              void* d_out, int out_size)
{
    const float* x = (const float*)d_in[0];
    const float* y = (const float*)d_in[1];
    float* out = (float*)d_out;

    dim3 grid(NTHREADS_TOTAL / THREADS);   // 2048 blocks
    dim3 block(THREADS);                   // 64 threads = 2 warps
    hcmp_kernel<<<grid, block>>>(x, y, out);
}